// round 5
// baseline (speedup 1.0000x reference)
#include <cuda_runtime.h>
#include <cstdint>

#define NNODES 64
#define NEDGES 128
#define NGRAPH 4

typedef unsigned long long ull;

// ---------------- scratch ----------------
__device__ float g_Y  [NNODES * 12000];
__device__ float g_Yp [16 * NNODES * 3000];
__device__ float g_xT [16 * NNODES];
__device__ float g_Pt [384 * NNODES];
__device__ float g_h1T[2000 * NNODES];
__device__ float g_h2T[500 * NNODES];
__device__ float g_h3 [NNODES * 100];

// ---------------- helpers ----------------
__device__ __forceinline__ void gdc_wait() {
    asm volatile("griddepcontrol.wait;" ::: "memory");
}
__device__ __forceinline__ ull dup2(float x) {
    ull r; asm("mov.b64 %0, {%1, %1};" : "=l"(r) : "f"(x)); return r;
}
__device__ __forceinline__ void fma2(ull &d, ull a, ull b) {
    asm("fma.rn.f32x2 %0, %1, %2, %3;" : "=l"(d) : "l"(a), "l"(b), "l"(d));
}
__device__ __forceinline__ float2 unpk(ull v) {
    float2 r; asm("mov.b64 {%0, %1}, %2;" : "=f"(r.x), "=f"(r.y) : "l"(v)); return r;
}
__device__ __forceinline__ void cpa16(void* dst, const void* src) {
    uint32_t d = (uint32_t)__cvta_generic_to_shared(dst);
    asm volatile("cp.async.cg.shared.global [%0], [%1], 16;\n" :: "r"(d), "l"(src));
}
__device__ __forceinline__ void cpa_commit() {
    asm volatile("cp.async.commit_group;\n" ::: "memory");
}
__device__ __forceinline__ void cpa_wait1() {
    asm volatile("cp.async.wait_group 1;\n" ::: "memory");
}
__device__ __forceinline__ void cpa_wait0() {
    asm volatile("cp.async.wait_group 0;\n" ::: "memory");
}

// ---------------- prep: xT + edge-structure matrix P ----------------
__global__ void prep(const float* __restrict__ x,
                     const int* __restrict__ eidx,
                     const float* __restrict__ eattr,
                     float* __restrict__ xT, float* __restrict__ Pt)
{
    gdc_wait();
    const int t = threadIdx.x;  // 128
    for (int i = t; i < 384 * NNODES; i += 128) Pt[i] = 0.f;
    if (t < NNODES)
        for (int a = 0; a < 9; a++) xT[a * NNODES + t] = x[t * 9 + a];
    __syncthreads();
    if (t < NEDGES) {
        int s = eidx[t], d = eidx[NEDGES + t];
        #pragma unroll
        for (int j = 0; j < 4; j++)
            atomicAdd(&Pt[(s * 5 + j) * NNODES + d], eattr[t * 4 + j]);
        atomicAdd(&Pt[(s * 5 + 4) * NNODES + d], 1.f);
    }
    __syncthreads();
    if (t < NNODES) Pt[(320 + t) * NNODES + t] = 1.f;
}

// ---------------- fused "concatenated-B" GEMM ----------------
// BM=64 (all rows), BN=128, BK=16, 128 threads, 8x8 thread tile (f32x2),
// double-buffered cp.async. Split-K slices -> Yp[by].
__global__ __launch_bounds__(128) void gemm_cat(
    const float* __restrict__ AT, int K, int O,
    const float* __restrict__ We, const float* __restrict__ be,
    const float* __restrict__ root, float* __restrict__ Yp, int kChunk)
{
    __shared__ float As[2][16][68];
    __shared__ float Bs[2][16][128];

    gdc_wait();

    const int t    = threadIdx.x;
    const int NC   = 6 * O;
    const int c0   = blockIdx.x * 128;
    const int k0   = blockIdx.y * kChunk;
    const int kend = min(k0 + kChunk, K);
    const int nsteps = (kend - k0 + 15) >> 4;

    // B staging: kk = t>>3, 4 chunks of 16B at cols (t&7)*16 + 4*i
    const int kkB   = t >> 3;
    const int cbase = (t & 7) * 16;
    const float4 z4 = make_float4(0.f, 0.f, 0.f, 0.f);

    auto stage = [&](int s, int buf) {
        const int kt = k0 + s * 16;
        const int kb = kend - kt;          // >=1; may exceed 16
        #pragma unroll
        for (int i = 0; i < 4; i++) {
            int cl = cbase + 4 * i;
            int c  = c0 + cl;
            float4* bd = (float4*)&Bs[buf][kkB][cl];
            if (kkB < kb && c < NC) {
                int blk = c / O;
                int o   = c - blk * O;
                const float* P = (blk < 4) ? (We + (size_t)blk * K * O)
                                           : ((blk == 4) ? be : root);
                cpa16(bd, P + (size_t)(kt + kkB) * O + o);
            } else *bd = z4;
        }
        #pragma unroll
        for (int i = 0; i < 2; i++) {
            int q  = t + 128 * i;
            int kk = q >> 4, m4 = (q & 15) * 4;
            float4* ad = (float4*)&As[buf][kk][m4];
            if (kk < kb) cpa16(ad, AT + (size_t)(kt + kk) * NNODES + m4);
            else         *ad = z4;
        }
        cpa_commit();
    };

    stage(0, 0);

    const int tx = t & 15;   // cols: c0 + 4*tx..+3  and  c0 + 64 + 4*tx..+3
    const int ty = t >> 4;   // rows: 8*ty .. 8*ty+7
    ull acc[4][8];           // [rowpair rp -> rows 8ty+2rp, +1][j: 0..3 low, 4..7 high]
    #pragma unroll
    for (int r = 0; r < 4; r++)
        #pragma unroll
        for (int j = 0; j < 8; j++) acc[r][j] = 0ull;

    for (int s = 0; s < nsteps; s++) {
        const int cur = s & 1;
        if (s + 1 < nsteps) { stage(s + 1, cur ^ 1); cpa_wait1(); }
        else                { cpa_wait0(); }
        __syncthreads();

        #pragma unroll
        for (int kk = 0; kk < 16; kk++) {
            const float* as = &As[cur][kk][8 * ty];
            ull a0 = *(const ull*)(as);
            ull a1 = *(const ull*)(as + 2);
            ull a2 = *(const ull*)(as + 4);
            ull a3 = *(const ull*)(as + 6);
            float4 bL = *(const float4*)&Bs[cur][kk][4 * tx];
            float4 bH = *(const float4*)&Bs[cur][kk][64 + 4 * tx];
            ull b0 = dup2(bL.x), b1 = dup2(bL.y), b2 = dup2(bL.z), b3 = dup2(bL.w);
            ull b4 = dup2(bH.x), b5 = dup2(bH.y), b6 = dup2(bH.z), b7 = dup2(bH.w);
            fma2(acc[0][0], a0, b0); fma2(acc[0][1], a0, b1); fma2(acc[0][2], a0, b2); fma2(acc[0][3], a0, b3);
            fma2(acc[0][4], a0, b4); fma2(acc[0][5], a0, b5); fma2(acc[0][6], a0, b6); fma2(acc[0][7], a0, b7);
            fma2(acc[1][0], a1, b0); fma2(acc[1][1], a1, b1); fma2(acc[1][2], a1, b2); fma2(acc[1][3], a1, b3);
            fma2(acc[1][4], a1, b4); fma2(acc[1][5], a1, b5); fma2(acc[1][6], a1, b6); fma2(acc[1][7], a1, b7);
            fma2(acc[2][0], a2, b0); fma2(acc[2][1], a2, b1); fma2(acc[2][2], a2, b2); fma2(acc[2][3], a2, b3);
            fma2(acc[2][4], a2, b4); fma2(acc[2][5], a2, b5); fma2(acc[2][6], a2, b6); fma2(acc[2][7], a2, b7);
            fma2(acc[3][0], a3, b0); fma2(acc[3][1], a3, b1); fma2(acc[3][2], a3, b2); fma2(acc[3][3], a3, b3);
            fma2(acc[3][4], a3, b4); fma2(acc[3][5], a3, b5); fma2(acc[3][6], a3, b6); fma2(acc[3][7], a3, b7);
        }
        __syncthreads();
    }

    float* Yo = Yp + (size_t)blockIdx.y * (NNODES * (size_t)NC);
    const int cL = c0 + 4 * tx;
    const int cH = c0 + 64 + 4 * tx;
    #pragma unroll
    for (int rp = 0; rp < 4; rp++) {
        int m = 8 * ty + 2 * rp;
        float2 vL0 = unpk(acc[rp][0]), vL1 = unpk(acc[rp][1]);
        float2 vL2 = unpk(acc[rp][2]), vL3 = unpk(acc[rp][3]);
        float2 vH0 = unpk(acc[rp][4]), vH1 = unpk(acc[rp][5]);
        float2 vH2 = unpk(acc[rp][6]), vH3 = unpk(acc[rp][7]);
        if (cL < NC) {
            *(float4*)&Yo[(size_t)m       * NC + cL] = make_float4(vL0.x, vL1.x, vL2.x, vL3.x);
            *(float4*)&Yo[(size_t)(m + 1) * NC + cL] = make_float4(vL0.y, vL1.y, vL2.y, vL3.y);
        }
        if (cH < NC) {
            *(float4*)&Yo[(size_t)m       * NC + cH] = make_float4(vH0.x, vH1.x, vH2.x, vH3.x);
            *(float4*)&Yo[(size_t)(m + 1) * NC + cH] = make_float4(vH0.y, vH1.y, vH2.y, vH3.y);
        }
    }
}

// ---------------- split-K reduction ----------------
__global__ void reduce_k(const float* __restrict__ Yp, float* __restrict__ Y,
                         int len, int S)
{
    gdc_wait();
    int i = blockIdx.x * 256 + threadIdx.x;
    if (i < len) {
        float s = 0.f;
        for (int j = 0; j < S; j++) s += Yp[(size_t)j * len + i];
        Y[i] = s;
    }
}

// ---------------- combine as GEMM: h = relu(P^T-mix of Y + b) ----------------
__global__ __launch_bounds__(128) void combine_gemm(
    const float* __restrict__ Y, int O, const float* __restrict__ Pt,
    const float* __restrict__ bias, float* __restrict__ h, float* __restrict__ hT)
{
    __shared__ float As[2][16][68];
    __shared__ float Bs[2][16][32];

    gdc_wait();

    const int t  = threadIdx.x;
    const int NC = 6 * O;
    const int c0 = blockIdx.x * 32;

    const int kkB = t >> 3;
    const int clB = (t & 7) * 4;
    const bool bvalid = (c0 + clB < O);
    const float4 z4 = make_float4(0.f, 0.f, 0.f, 0.f);

    auto stage = [&](int s, int buf) {
        int kt = s * 16;
        {
            int r = kt + kkB;
            int sN, jb;
            if (r < 320) { sN = r / 5; jb = r - 5 * sN; }
            else         { sN = r - 320; jb = 5; }
            float4* bd = (float4*)&Bs[buf][kkB][clB];
            if (bvalid) cpa16(bd, Y + (size_t)sN * NC + (size_t)jb * O + c0 + clB);
            else        *bd = z4;
        }
        #pragma unroll
        for (int i = 0; i < 2; i++) {
            int q  = t + 128 * i;
            int kk = q >> 4;
            int m4 = (q & 15) * 4;
            cpa16(&As[buf][kk][m4], Pt + (size_t)(kt + kk) * NNODES + m4);
        }
        cpa_commit();
    };

    stage(0, 0);

    const int tx = t & 7;
    const int ty = t >> 3;
    ull acc[2][4];
    #pragma unroll
    for (int r = 0; r < 2; r++)
        #pragma unroll
        for (int j = 0; j < 4; j++) acc[r][j] = 0ull;

    for (int s = 0; s < 24; s++) {
        const int cur = s & 1;
        if (s + 1 < 24) { stage(s + 1, cur ^ 1); cpa_wait1(); }
        else            { cpa_wait0(); }
        __syncthreads();

        #pragma unroll
        for (int kk = 0; kk < 16; kk++) {
            const float* as = &As[cur][kk][0];
            ull a0 = *(const ull*)(as + 4 * ty);
            ull a1 = *(const ull*)(as + 4 * ty + 2);
            float4 b = *(const float4*)&Bs[cur][kk][4 * tx];
            ull b0 = dup2(b.x), b1 = dup2(b.y), b2 = dup2(b.z), b3 = dup2(b.w);
            fma2(acc[0][0], a0, b0); fma2(acc[0][1], a0, b1);
            fma2(acc[0][2], a0, b2); fma2(acc[0][3], a0, b3);
            fma2(acc[1][0], a1, b0); fma2(acc[1][1], a1, b1);
            fma2(acc[1][2], a1, b2); fma2(acc[1][3], a1, b3);
        }
        __syncthreads();
    }

    const int c = c0 + 4 * tx;
    if (c < O) {
        float4 bb = *(const float4*)&bias[c];
        float2 v[2][4];
        #pragma unroll
        for (int r = 0; r < 2; r++)
            #pragma unroll
            for (int j = 0; j < 4; j++) v[r][j] = unpk(acc[r][j]);
        float row[4][4];
        #pragma unroll
        for (int j = 0; j < 4; j++) {
            float bj = (&bb.x)[j];
            row[0][j] = fmaxf(v[0][j].x + bj, 0.f);
            row[1][j] = fmaxf(v[0][j].y + bj, 0.f);
            row[2][j] = fmaxf(v[1][j].x + bj, 0.f);
            row[3][j] = fmaxf(v[1][j].y + bj, 0.f);
        }
        const int m0 = 4 * ty;
        #pragma unroll
        for (int r = 0; r < 4; r++)
            *(float4*)&h[(size_t)(m0 + r) * O + c] =
                make_float4(row[r][0], row[r][1], row[r][2], row[r][3]);
        #pragma unroll
        for (int j = 0; j < 4; j++)
            *(float4*)&hT[(size_t)(c + j) * NNODES + m0] =
                make_float4(row[0][j], row[1][j], row[2][j], row[3][j]);
    }
}

// ---------------- fused FCN head ----------------
__global__ __launch_bounds__(256) void head_fused(
    const float* __restrict__ h3, const int* __restrict__ batch,
    const float* __restrict__ W1, const float* __restrict__ c1,
    const float* __restrict__ W2, const float* __restrict__ c2,
    const float* __restrict__ W3, const float* __restrict__ c3,
    const float* __restrict__ W4, const float* __restrict__ c4,
    float* __restrict__ out)
{
    __shared__ float gS[100];
    __shared__ float s1[1000];
    __shared__ float part[200];
    __shared__ float s2[100];
    __shared__ float s3[50];
    __shared__ int   sb[NNODES];

    gdc_wait();

    const int g = blockIdx.x;
    const int t = threadIdx.x;

    if (t < NNODES) sb[t] = batch[t];
    __syncthreads();

    if (t < 100) {
        float a = 0.f;
        for (int n = 0; n < NNODES; n++)
            if (sb[n] == g) a += h3[n * 100 + t];
        gS[t] = a;
    }
    __syncthreads();

    for (int f = t; f < 1000; f += 256) {
        float a = c1[f];
        for (int k = 0; k < 100; k++) a += gS[k] * W1[k * 1000 + f];
        s1[f] = fmaxf(a, 0.f);
    }
    __syncthreads();

    if (t < 200) {
        int f = t % 100, hh = t / 100;
        float a = 0.f;
        int k0 = hh * 500;
        for (int k = k0; k < k0 + 500; k++) a += s1[k] * W2[k * 100 + f];
        part[t] = a;
    }
    __syncthreads();
    if (t < 100) s2[t] = fmaxf(part[t] + part[100 + t] + c2[t], 0.f);
    __syncthreads();

    if (t < 50) {
        float a = c3[t];
        for (int k = 0; k < 100; k++) a += s2[k] * W3[k * 50 + t];
        s3[t] = fmaxf(a, 0.f);
    }
    __syncthreads();

    if (t < 32) {
        float a = (t < 50) ? s3[t] * W4[t] : 0.f;
        if (t + 32 < 50) a += s3[t + 32] * W4[t + 32];
        #pragma unroll
        for (int o = 16; o > 0; o >>= 1)
            a += __shfl_xor_sync(0xffffffffu, a, o);
        if (t == 0) out[g] = a + c4[0];
    }
}

// ---------------- launch (all nodes PDL-chained) ----------------
extern "C" void kernel_launch(void* const* d_in, const int* in_sizes, int n_in,
                              void* d_out, int out_size)
{
    const float* x     = (const float*)d_in[0];
    const int*   eidx  = (const int*)  d_in[1];
    const float* eattr = (const float*)d_in[2];
    const int*   batch = (const int*)  d_in[3];
    const float *We1 = (const float*)d_in[4],  *be1 = (const float*)d_in[5];
    const float *ro1 = (const float*)d_in[6],  *b1  = (const float*)d_in[7];
    const float *We2 = (const float*)d_in[8],  *be2 = (const float*)d_in[9];
    const float *ro2 = (const float*)d_in[10], *b2  = (const float*)d_in[11];
    const float *We3 = (const float*)d_in[12], *be3 = (const float*)d_in[13];
    const float *ro3 = (const float*)d_in[14], *b3  = (const float*)d_in[15];
    const float *W1  = (const float*)d_in[16], *c1  = (const float*)d_in[17];
    const float *W2  = (const float*)d_in[18], *c2  = (const float*)d_in[19];
    const float *W3  = (const float*)d_in[20], *c3  = (const float*)d_in[21];
    const float *W4  = (const float*)d_in[22], *c4  = (const float*)d_in[23];

    float *Y, *Yp, *xT, *Pt, *h1T, *h2T, *h3;
    cudaGetSymbolAddress((void**)&Y,   g_Y);
    cudaGetSymbolAddress((void**)&Yp,  g_Yp);
    cudaGetSymbolAddress((void**)&xT,  g_xT);
    cudaGetSymbolAddress((void**)&Pt,  g_Pt);
    cudaGetSymbolAddress((void**)&h1T, g_h1T);
    cudaGetSymbolAddress((void**)&h2T, g_h2T);
    cudaGetSymbolAddress((void**)&h3,  g_h3);

    cudaLaunchAttribute attr;
    attr.id = cudaLaunchAttributeProgrammaticStreamSerialization;
    attr.val.programmaticStreamSerializationAllowed = 1;

    auto mkcfg = [&](int gx, int gy, int nt) {
        cudaLaunchConfig_t cf{};
        cf.gridDim = dim3((unsigned)gx, (unsigned)gy, 1);
        cf.blockDim = dim3((unsigned)nt, 1, 1);
        cf.dynamicSmemBytes = 0;
        cf.stream = 0;
        cf.attrs = &attr;
        cf.numAttrs = 1;
        return cf;
    };

    cudaLaunchConfig_t cf;

    cf = mkcfg(1, 1, 128);
    cudaLaunchKernelEx(&cf, prep, x, eidx, eattr, xT, Pt);

    // Layer 1: K=9, O=2000, NC=12000 -> 94 col tiles (BN=128), no split-K
    cf = mkcfg(94, 1, 128);
    cudaLaunchKernelEx(&cf, gemm_cat, (const float*)xT, 9, 2000, We1, be1, ro1, Y, 16);
    cf = mkcfg(63, 1, 128);
    cudaLaunchKernelEx(&cf, combine_gemm, (const float*)Y, 2000, (const float*)Pt, b1, Yp, h1T);

    // Layer 2: K=2000, O=500, NC=3000 -> 24 tiles x 6 K-slices (one wave)
    cf = mkcfg(24, 6, 128);
    cudaLaunchKernelEx(&cf, gemm_cat, (const float*)h1T, 2000, 500, We2, be2, ro2, Yp, 334);
    cf = mkcfg((NNODES * 3000 + 255) / 256, 1, 256);
    cudaLaunchKernelEx(&cf, reduce_k, (const float*)Yp, Y, NNODES * 3000, 6);
    cf = mkcfg(16, 1, 128);
    cudaLaunchKernelEx(&cf, combine_gemm, (const float*)Y, 500, (const float*)Pt, b2, Yp, h2T);

    // Layer 3: K=500, O=100, NC=600 -> 5 tiles x 25 K-slices
    cf = mkcfg(5, 25, 128);
    cudaLaunchKernelEx(&cf, gemm_cat, (const float*)h2T, 500, 100, We3, be3, ro3, Yp, 20);
    cf = mkcfg((NNODES * 600 + 255) / 256, 1, 256);
    cudaLaunchKernelEx(&cf, reduce_k, (const float*)Yp, Y, NNODES * 600, 25);
    cf = mkcfg(4, 1, 128);
    cudaLaunchKernelEx(&cf, combine_gemm, (const float*)Y, 100, (const float*)Pt, b3, h3, h2T);

    // Head
    cf = mkcfg(NGRAPH, 1, 256);
    cudaLaunchKernelEx(&cf, head_fused, (const float*)h3, batch, W1, c1, W2, c2,
                       W3, c3, W4, c4, (float*)d_out);
}

// round 6
// speedup vs baseline: 1.0533x; 1.0533x over previous
#include <cuda_runtime.h>
#include <cstdint>

#define NNODES 64
#define NEDGES 128
#define NGRAPH 4

typedef unsigned long long ull;

// ---------------- scratch ----------------
__device__ float g_Y  [NNODES * 12000];
__device__ float g_Yp [16 * NNODES * 3000];
__device__ float g_xT [16 * NNODES];
__device__ float g_Pt [384 * NNODES];
__device__ float g_h1T[2000 * NNODES];
__device__ float g_h2T[500 * NNODES];
__device__ float g_h3 [NNODES * 100];

// ---------------- helpers ----------------
__device__ __forceinline__ void gdc_wait() {
    asm volatile("griddepcontrol.wait;" ::: "memory");
}
__device__ __forceinline__ ull dup2(float x) {
    ull r; asm("mov.b64 %0, {%1, %1};" : "=l"(r) : "f"(x)); return r;
}
__device__ __forceinline__ void fma2(ull &d, ull a, ull b) {
    asm("fma.rn.f32x2 %0, %1, %2, %3;" : "=l"(d) : "l"(a), "l"(b), "l"(d));
}
__device__ __forceinline__ float2 unpk(ull v) {
    float2 r; asm("mov.b64 {%0, %1}, %2;" : "=f"(r.x), "=f"(r.y) : "l"(v)); return r;
}
__device__ __forceinline__ void cpa16(void* dst, const void* src) {
    uint32_t d = (uint32_t)__cvta_generic_to_shared(dst);
    asm volatile("cp.async.cg.shared.global [%0], [%1], 16;\n" :: "r"(d), "l"(src));
}
__device__ __forceinline__ void cpa_commit() {
    asm volatile("cp.async.commit_group;\n" ::: "memory");
}
__device__ __forceinline__ void cpa_wait1() {
    asm volatile("cp.async.wait_group 1;\n" ::: "memory");
}
__device__ __forceinline__ void cpa_wait0() {
    asm volatile("cp.async.wait_group 0;\n" ::: "memory");
}

// ---------------- prep: xT + edge-structure matrix P ----------------
__global__ void prep(const float* __restrict__ x,
                     const int* __restrict__ eidx,
                     const float* __restrict__ eattr,
                     float* __restrict__ xT, float* __restrict__ Pt)
{
    gdc_wait();
    const int t = threadIdx.x;  // 128
    for (int i = t; i < 384 * NNODES; i += 128) Pt[i] = 0.f;
    if (t < NNODES)
        for (int a = 0; a < 9; a++) xT[a * NNODES + t] = x[t * 9 + a];
    __syncthreads();
    if (t < NEDGES) {
        int s = eidx[t], d = eidx[NEDGES + t];
        #pragma unroll
        for (int j = 0; j < 4; j++)
            atomicAdd(&Pt[(s * 5 + j) * NNODES + d], eattr[t * 4 + j]);
        atomicAdd(&Pt[(s * 5 + 4) * NNODES + d], 1.f);
    }
    __syncthreads();
    if (t < NNODES) Pt[(320 + t) * NNODES + t] = 1.f;
}

// ---------------- fused "concatenated-B" GEMM ----------------
// BM=64 (all rows), BN=128, BK=16, 128 threads, 8x8 thread tile (f32x2),
// double-buffered cp.async. Split-K slices -> Yp[by].
__global__ __launch_bounds__(128) void gemm_cat(
    const float* __restrict__ AT, int K, int O,
    const float* __restrict__ We, const float* __restrict__ be,
    const float* __restrict__ root, float* __restrict__ Yp, int kChunk)
{
    __shared__ float As[2][16][68];
    __shared__ float Bs[2][16][128];

    gdc_wait();

    const int t    = threadIdx.x;
    const int NC   = 6 * O;
    const int c0   = blockIdx.x * 128;
    const int k0   = blockIdx.y * kChunk;
    const int kend = min(k0 + kChunk, K);
    const int nsteps = (kend - k0 + 15) >> 4;

    const int kkB   = t >> 3;
    const int cbase = (t & 7) * 16;
    const float4 z4 = make_float4(0.f, 0.f, 0.f, 0.f);

    auto stage = [&](int s, int buf) {
        const int kt = k0 + s * 16;
        const int kb = kend - kt;
        #pragma unroll
        for (int i = 0; i < 4; i++) {
            int cl = cbase + 4 * i;
            int c  = c0 + cl;
            float4* bd = (float4*)&Bs[buf][kkB][cl];
            if (kkB < kb && c < NC) {
                int blk = c / O;
                int o   = c - blk * O;
                const float* P = (blk < 4) ? (We + (size_t)blk * K * O)
                                           : ((blk == 4) ? be : root);
                cpa16(bd, P + (size_t)(kt + kkB) * O + o);
            } else *bd = z4;
        }
        #pragma unroll
        for (int i = 0; i < 2; i++) {
            int q  = t + 128 * i;
            int kk = q >> 4, m4 = (q & 15) * 4;
            float4* ad = (float4*)&As[buf][kk][m4];
            if (kk < kb) cpa16(ad, AT + (size_t)(kt + kk) * NNODES + m4);
            else         *ad = z4;
        }
        cpa_commit();
    };

    stage(0, 0);

    const int tx = t & 15;
    const int ty = t >> 4;
    ull acc[4][8];
    #pragma unroll
    for (int r = 0; r < 4; r++)
        #pragma unroll
        for (int j = 0; j < 8; j++) acc[r][j] = 0ull;

    for (int s = 0; s < nsteps; s++) {
        const int cur = s & 1;
        if (s + 1 < nsteps) { stage(s + 1, cur ^ 1); cpa_wait1(); }
        else                { cpa_wait0(); }
        __syncthreads();

        #pragma unroll
        for (int kk = 0; kk < 16; kk++) {
            const float* as = &As[cur][kk][8 * ty];
            ull a0 = *(const ull*)(as);
            ull a1 = *(const ull*)(as + 2);
            ull a2 = *(const ull*)(as + 4);
            ull a3 = *(const ull*)(as + 6);
            float4 bL = *(const float4*)&Bs[cur][kk][4 * tx];
            float4 bH = *(const float4*)&Bs[cur][kk][64 + 4 * tx];
            ull b0 = dup2(bL.x), b1 = dup2(bL.y), b2 = dup2(bL.z), b3 = dup2(bL.w);
            ull b4 = dup2(bH.x), b5 = dup2(bH.y), b6 = dup2(bH.z), b7 = dup2(bH.w);
            fma2(acc[0][0], a0, b0); fma2(acc[0][1], a0, b1); fma2(acc[0][2], a0, b2); fma2(acc[0][3], a0, b3);
            fma2(acc[0][4], a0, b4); fma2(acc[0][5], a0, b5); fma2(acc[0][6], a0, b6); fma2(acc[0][7], a0, b7);
            fma2(acc[1][0], a1, b0); fma2(acc[1][1], a1, b1); fma2(acc[1][2], a1, b2); fma2(acc[1][3], a1, b3);
            fma2(acc[1][4], a1, b4); fma2(acc[1][5], a1, b5); fma2(acc[1][6], a1, b6); fma2(acc[1][7], a1, b7);
            fma2(acc[2][0], a2, b0); fma2(acc[2][1], a2, b1); fma2(acc[2][2], a2, b2); fma2(acc[2][3], a2, b3);
            fma2(acc[2][4], a2, b4); fma2(acc[2][5], a2, b5); fma2(acc[2][6], a2, b6); fma2(acc[2][7], a2, b7);
            fma2(acc[3][0], a3, b0); fma2(acc[3][1], a3, b1); fma2(acc[3][2], a3, b2); fma2(acc[3][3], a3, b3);
            fma2(acc[3][4], a3, b4); fma2(acc[3][5], a3, b5); fma2(acc[3][6], a3, b6); fma2(acc[3][7], a3, b7);
        }
        __syncthreads();
    }

    float* Yo = Yp + (size_t)blockIdx.y * (NNODES * (size_t)NC);
    const int cL = c0 + 4 * tx;
    const int cH = c0 + 64 + 4 * tx;
    #pragma unroll
    for (int rp = 0; rp < 4; rp++) {
        int m = 8 * ty + 2 * rp;
        float2 vL0 = unpk(acc[rp][0]), vL1 = unpk(acc[rp][1]);
        float2 vL2 = unpk(acc[rp][2]), vL3 = unpk(acc[rp][3]);
        float2 vH0 = unpk(acc[rp][4]), vH1 = unpk(acc[rp][5]);
        float2 vH2 = unpk(acc[rp][6]), vH3 = unpk(acc[rp][7]);
        if (cL < NC) {
            *(float4*)&Yo[(size_t)m       * NC + cL] = make_float4(vL0.x, vL1.x, vL2.x, vL3.x);
            *(float4*)&Yo[(size_t)(m + 1) * NC + cL] = make_float4(vL0.y, vL1.y, vL2.y, vL3.y);
        }
        if (cH < NC) {
            *(float4*)&Yo[(size_t)m       * NC + cH] = make_float4(vH0.x, vH1.x, vH2.x, vH3.x);
            *(float4*)&Yo[(size_t)(m + 1) * NC + cH] = make_float4(vH0.y, vH1.y, vH2.y, vH3.y);
        }
    }
}

// ---------------- split-K reduction ----------------
__global__ void reduce_k(const float* __restrict__ Yp, float* __restrict__ Y,
                         int len, int S)
{
    gdc_wait();
    int i = blockIdx.x * 256 + threadIdx.x;
    if (i < len) {
        float s = 0.f;
        for (int j = 0; j < S; j++) s += Yp[(size_t)j * len + i];
        Y[i] = s;
    }
}

// ---------------- combine as GEMM: h = relu(P^T-mix of Y + b) ----------------
__global__ __launch_bounds__(128) void combine_gemm(
    const float* __restrict__ Y, int O, const float* __restrict__ Pt,
    const float* __restrict__ bias, float* __restrict__ h, float* __restrict__ hT)
{
    __shared__ float As[2][16][68];
    __shared__ float Bs[2][16][32];

    gdc_wait();

    const int t  = threadIdx.x;
    const int NC = 6 * O;
    const int c0 = blockIdx.x * 32;

    const int kkB = t >> 3;
    const int clB = (t & 7) * 4;
    const bool bvalid = (c0 + clB < O);
    const float4 z4 = make_float4(0.f, 0.f, 0.f, 0.f);

    auto stage = [&](int s, int buf) {
        int kt = s * 16;
        {
            int r = kt + kkB;
            int sN, jb;
            if (r < 320) { sN = r / 5; jb = r - 5 * sN; }
            else         { sN = r - 320; jb = 5; }
            float4* bd = (float4*)&Bs[buf][kkB][clB];
            if (bvalid) cpa16(bd, Y + (size_t)sN * NC + (size_t)jb * O + c0 + clB);
            else        *bd = z4;
        }
        #pragma unroll
        for (int i = 0; i < 2; i++) {
            int q  = t + 128 * i;
            int kk = q >> 4;
            int m4 = (q & 15) * 4;
            cpa16(&As[buf][kk][m4], Pt + (size_t)(kt + kk) * NNODES + m4);
        }
        cpa_commit();
    };

    stage(0, 0);

    const int tx = t & 7;
    const int ty = t >> 3;
    ull acc[2][4];
    #pragma unroll
    for (int r = 0; r < 2; r++)
        #pragma unroll
        for (int j = 0; j < 4; j++) acc[r][j] = 0ull;

    for (int s = 0; s < 24; s++) {
        const int cur = s & 1;
        if (s + 1 < 24) { stage(s + 1, cur ^ 1); cpa_wait1(); }
        else            { cpa_wait0(); }
        __syncthreads();

        #pragma unroll
        for (int kk = 0; kk < 16; kk++) {
            const float* as = &As[cur][kk][0];
            ull a0 = *(const ull*)(as + 4 * ty);
            ull a1 = *(const ull*)(as + 4 * ty + 2);
            float4 b = *(const float4*)&Bs[cur][kk][4 * tx];
            ull b0 = dup2(b.x), b1 = dup2(b.y), b2 = dup2(b.z), b3 = dup2(b.w);
            fma2(acc[0][0], a0, b0); fma2(acc[0][1], a0, b1);
            fma2(acc[0][2], a0, b2); fma2(acc[0][3], a0, b3);
            fma2(acc[1][0], a1, b0); fma2(acc[1][1], a1, b1);
            fma2(acc[1][2], a1, b2); fma2(acc[1][3], a1, b3);
        }
        __syncthreads();
    }

    const int c = c0 + 4 * tx;
    if (c < O) {
        float4 bb = *(const float4*)&bias[c];
        float2 v[2][4];
        #pragma unroll
        for (int r = 0; r < 2; r++)
            #pragma unroll
            for (int j = 0; j < 4; j++) v[r][j] = unpk(acc[r][j]);
        float row[4][4];
        #pragma unroll
        for (int j = 0; j < 4; j++) {
            float bj = (&bb.x)[j];
            row[0][j] = fmaxf(v[0][j].x + bj, 0.f);
            row[1][j] = fmaxf(v[0][j].y + bj, 0.f);
            row[2][j] = fmaxf(v[1][j].x + bj, 0.f);
            row[3][j] = fmaxf(v[1][j].y + bj, 0.f);
        }
        const int m0 = 4 * ty;
        #pragma unroll
        for (int r = 0; r < 4; r++)
            *(float4*)&h[(size_t)(m0 + r) * O + c] =
                make_float4(row[r][0], row[r][1], row[r][2], row[r][3]);
        #pragma unroll
        for (int j = 0; j < 4; j++)
            *(float4*)&hT[(size_t)(c + j) * NNODES + m0] =
                make_float4(row[0][j], row[1][j], row[2][j], row[3][j]);
    }
}

// ---------------- fused FCN head ----------------
__global__ __launch_bounds__(256) void head_fused(
    const float* __restrict__ h3, const int* __restrict__ batch,
    const float* __restrict__ W1, const float* __restrict__ c1,
    const float* __restrict__ W2, const float* __restrict__ c2,
    const float* __restrict__ W3, const float* __restrict__ c3,
    const float* __restrict__ W4, const float* __restrict__ c4,
    float* __restrict__ out)
{
    __shared__ float gS[100];
    __shared__ float s1[1000];
    __shared__ float part[200];
    __shared__ float s2[100];
    __shared__ float s3[50];
    __shared__ int   sb[NNODES];

    gdc_wait();

    const int g = blockIdx.x;
    const int t = threadIdx.x;

    if (t < NNODES) sb[t] = batch[t];
    __syncthreads();

    if (t < 100) {
        float a = 0.f;
        for (int n = 0; n < NNODES; n++)
            if (sb[n] == g) a += h3[n * 100 + t];
        gS[t] = a;
    }
    __syncthreads();

    for (int f = t; f < 1000; f += 256) {
        float a = c1[f];
        for (int k = 0; k < 100; k++) a += gS[k] * W1[k * 1000 + f];
        s1[f] = fmaxf(a, 0.f);
    }
    __syncthreads();

    if (t < 200) {
        int f = t % 100, hh = t / 100;
        float a = 0.f;
        int k0 = hh * 500;
        for (int k = k0; k < k0 + 500; k++) a += s1[k] * W2[k * 100 + f];
        part[t] = a;
    }
    __syncthreads();
    if (t < 100) s2[t] = fmaxf(part[t] + part[100 + t] + c2[t], 0.f);
    __syncthreads();

    if (t < 50) {
        float a = c3[t];
        for (int k = 0; k < 100; k++) a += s2[k] * W3[k * 50 + t];
        s3[t] = fmaxf(a, 0.f);
    }
    __syncthreads();

    if (t < 32) {
        float a = (t < 50) ? s3[t] * W4[t] : 0.f;
        if (t + 32 < 50) a += s3[t + 32] * W4[t + 32];
        #pragma unroll
        for (int o = 16; o > 0; o >>= 1)
            a += __shfl_xor_sync(0xffffffffu, a, o);
        if (t == 0) out[g] = a + c4[0];
    }
}

// ---------------- launch (all nodes PDL-chained) ----------------
extern "C" void kernel_launch(void* const* d_in, const int* in_sizes, int n_in,
                              void* d_out, int out_size)
{
    const float* x     = (const float*)d_in[0];
    const int*   eidx  = (const int*)  d_in[1];
    const float* eattr = (const float*)d_in[2];
    const int*   batch = (const int*)  d_in[3];
    const float *We1 = (const float*)d_in[4],  *be1 = (const float*)d_in[5];
    const float *ro1 = (const float*)d_in[6],  *b1  = (const float*)d_in[7];
    const float *We2 = (const float*)d_in[8],  *be2 = (const float*)d_in[9];
    const float *ro2 = (const float*)d_in[10], *b2  = (const float*)d_in[11];
    const float *We3 = (const float*)d_in[12], *be3 = (const float*)d_in[13];
    const float *ro3 = (const float*)d_in[14], *b3  = (const float*)d_in[15];
    const float *W1  = (const float*)d_in[16], *c1  = (const float*)d_in[17];
    const float *W2  = (const float*)d_in[18], *c2  = (const float*)d_in[19];
    const float *W3  = (const float*)d_in[20], *c3  = (const float*)d_in[21];
    const float *W4  = (const float*)d_in[22], *c4  = (const float*)d_in[23];

    float *Y, *Yp, *xT, *Pt, *h1T, *h2T, *h3;
    cudaGetSymbolAddress((void**)&Y,   g_Y);
    cudaGetSymbolAddress((void**)&Yp,  g_Yp);
    cudaGetSymbolAddress((void**)&xT,  g_xT);
    cudaGetSymbolAddress((void**)&Pt,  g_Pt);
    cudaGetSymbolAddress((void**)&h1T, g_h1T);
    cudaGetSymbolAddress((void**)&h2T, g_h2T);
    cudaGetSymbolAddress((void**)&h3,  g_h3);

    cudaLaunchAttribute attr;
    attr.id = cudaLaunchAttributeProgrammaticStreamSerialization;
    attr.val.programmaticStreamSerializationAllowed = 1;

    auto mkcfg = [&](int gx, int gy, int nt) {
        cudaLaunchConfig_t cf{};
        cf.gridDim = dim3((unsigned)gx, (unsigned)gy, 1);
        cf.blockDim = dim3((unsigned)nt, 1, 1);
        cf.dynamicSmemBytes = 0;
        cf.stream = 0;
        cf.attrs = &attr;
        cf.numAttrs = 1;
        return cf;
    };

    cudaLaunchConfig_t cf;

    cf = mkcfg(1, 1, 128);
    cudaLaunchKernelEx(&cf, prep, x, eidx, eattr, xT, Pt);

    // Layer 1: K=9, O=2000, NC=12000 -> 94 col tiles (BN=128), no split-K
    cf = mkcfg(94, 1, 128);
    cudaLaunchKernelEx(&cf, gemm_cat, (const float*)xT, 9, 2000, We1, be1, ro1, Y, 16);
    cf = mkcfg(63, 1, 128);
    cudaLaunchKernelEx(&cf, combine_gemm, (const float*)Y, 2000, (const float*)Pt, b1, Yp, h1T);

    // Layer 2: K=2000, O=500, NC=3000 -> 24 tiles x 12 K-slices (288 blocks, ~2/SM)
    cf = mkcfg(24, 12, 128);
    cudaLaunchKernelEx(&cf, gemm_cat, (const float*)h1T, 2000, 500, We2, be2, ro2, Yp, 168);
    cf = mkcfg((NNODES * 3000 + 255) / 256, 1, 256);
    cudaLaunchKernelEx(&cf, reduce_k, (const float*)Yp, Y, NNODES * 3000, 12);
    cf = mkcfg(16, 1, 128);
    cudaLaunchKernelEx(&cf, combine_gemm, (const float*)Y, 500, (const float*)Pt, b2, Yp, h2T);

    // Layer 3: K=500, O=100, NC=600 -> 5 tiles x 32 K-slices (160 blocks)
    cf = mkcfg(5, 32, 128);
    cudaLaunchKernelEx(&cf, gemm_cat, (const float*)h2T, 500, 100, We3, be3, ro3, Yp, 16);
    cf = mkcfg((NNODES * 600 + 255) / 256, 1, 256);
    cudaLaunchKernelEx(&cf, reduce_k, (const float*)Yp, Y, NNODES * 600, 32);
    cf = mkcfg(4, 1, 128);
    cudaLaunchKernelEx(&cf, combine_gemm, (const float*)Y, 100, (const float*)Pt, b3, h3, h2T);

    // Head
    cf = mkcfg(NGRAPH, 1, 256);
    cudaLaunchKernelEx(&cf, head_fused, (const float*)h3, batch, W1, c1, W2, c2,
                       W3, c3, W4, c4, (float*)d_out);
}